// round 3
// baseline (speedup 1.0000x reference)
#include <cuda_runtime.h>
#include <cstdint>

// Problem dims (fixed)
#define TOK   8192      // B*N
#define DIM   1024      // D
#define NCB   64        // C codebooks
#define KD    16        // K
#define NP    64        // P keys
#define MV    128       // M
#define NR    8         // R
#define NPROJ 2048      // 2 branches * C*K

// 64 MB scratch for projections: proj[t][n], n = branch*1024 + c*16 + k
__device__ float g_proj[(size_t)TOK * NPROJ];

// ---------------------------------------------------------------------------
// Kernel 1: fp32 SGEMM  proj[t, n] = sum_d x[t,d] * W[n,d]
// 128x128 tile, BK=8, 256 threads, 8x8 micro-tile, double-buffered smem,
// one __syncthreads per k-step, global prefetch into registers.
// ---------------------------------------------------------------------------
__global__ __launch_bounds__(256) void proj_gemm(
    const float* __restrict__ X,
    const float* __restrict__ WA,
    const float* __restrict__ WB,
    float* __restrict__ out)
{
    const int n0 = blockIdx.x * 128;   // 0..1920
    const int t0 = blockIdx.y * 128;   // 0..8064
    const float* __restrict__ W = (n0 < 1024) ? (WA + (size_t)n0 * DIM)
                                              : (WB + (size_t)(n0 - 1024) * DIM);

    __shared__ float As[2][8][128];
    __shared__ float Bs[2][8][128];

    const int tid = threadIdx.x;
    const int tx = tid & 15;       // 0..15 -> n
    const int ty = tid >> 4;       // 0..15 -> t
    const int lr = tid >> 1;       // 0..127 load row
    const int lc = (tid & 1) * 4;  // 0 or 4 load col

    float acc[8][8];
    #pragma unroll
    for (int i = 0; i < 8; i++)
        #pragma unroll
        for (int j = 0; j < 8; j++) acc[i][j] = 0.f;

    const float* aptr = X + (size_t)(t0 + lr) * DIM + lc;
    const float* bptr = W + (size_t)lr * DIM + lc;

    // preload k0 = 0
    float4 av = *(const float4*)(aptr);
    float4 bv = *(const float4*)(bptr);
    As[0][lc + 0][lr] = av.x; As[0][lc + 1][lr] = av.y;
    As[0][lc + 2][lr] = av.z; As[0][lc + 3][lr] = av.w;
    Bs[0][lc + 0][lr] = bv.x; Bs[0][lc + 1][lr] = bv.y;
    Bs[0][lc + 2][lr] = bv.z; Bs[0][lc + 3][lr] = bv.w;
    __syncthreads();

    int buf = 0;
    for (int k0 = 8; k0 < DIM; k0 += 8) {
        // issue next-tile loads early (hidden under compute)
        av = *(const float4*)(aptr + k0);
        bv = *(const float4*)(bptr + k0);

        #pragma unroll
        for (int kk = 0; kk < 8; kk++) {
            float ra[8], rb[8];
            #pragma unroll
            for (int i = 0; i < 8; i++) ra[i] = As[buf][kk][ty * 8 + i];
            #pragma unroll
            for (int j = 0; j < 8; j++) rb[j] = Bs[buf][kk][tx * 8 + j];
            #pragma unroll
            for (int i = 0; i < 8; i++)
                #pragma unroll
                for (int j = 0; j < 8; j++)
                    acc[i][j] = fmaf(ra[i], rb[j], acc[i][j]);
        }

        const int nb = buf ^ 1;
        As[nb][lc + 0][lr] = av.x; As[nb][lc + 1][lr] = av.y;
        As[nb][lc + 2][lr] = av.z; As[nb][lc + 3][lr] = av.w;
        Bs[nb][lc + 0][lr] = bv.x; Bs[nb][lc + 1][lr] = bv.y;
        Bs[nb][lc + 2][lr] = bv.z; Bs[nb][lc + 3][lr] = bv.w;
        __syncthreads();
        buf = nb;
    }

    // last tile
    #pragma unroll
    for (int kk = 0; kk < 8; kk++) {
        float ra[8], rb[8];
        #pragma unroll
        for (int i = 0; i < 8; i++) ra[i] = As[buf][kk][ty * 8 + i];
        #pragma unroll
        for (int j = 0; j < 8; j++) rb[j] = Bs[buf][kk][tx * 8 + j];
        #pragma unroll
        for (int i = 0; i < 8; i++)
            #pragma unroll
            for (int j = 0; j < 8; j++)
                acc[i][j] = fmaf(ra[i], rb[j], acc[i][j]);
    }

    #pragma unroll
    for (int i = 0; i < 8; i++) {
        float* orow = out + (size_t)(t0 + ty * 8 + i) * NPROJ + n0 + tx * 8;
        *(float4*)(orow + 0) = make_float4(acc[i][0], acc[i][1], acc[i][2], acc[i][3]);
        *(float4*)(orow + 4) = make_float4(acc[i][4], acc[i][5], acc[i][6], acc[i][7]);
    }
}

// ---------------------------------------------------------------------------
// Kernel 2: fused argmin + gather-dot + output.  8 tokens per block.
// proj read straight from gmem (each element consumed exactly once per block,
// so smem staging buys nothing and kills occupancy). Only x is staged.
// ---------------------------------------------------------------------------
#define GTOK 8

__device__ __forceinline__ unsigned ord_f32(float f) {
    unsigned b = __float_as_uint(f);
    return (b & 0x80000000u) ? ~b : (b | 0x80000000u);  // monotonic map
}

__global__ __launch_bounds__(256) void fuse_kernel(
    const float* __restrict__ x,
    const float* __restrict__ proj,
    const float* __restrict__ emb_A, const float* __restrict__ vals_A,
    const float* __restrict__ emb_B, const float* __restrict__ vals_B,
    float* __restrict__ out)
{
    __shared__ float x_s[GTOK * DIM];        // 32 KB
    __shared__ float sA[GTOK * NCB];
    __shared__ float tb[GTOK * NR];
    __shared__ int   idxA[GTOK * NCB];
    __shared__ int   idxB[GTOK * NCB];

    const int tid  = threadIdx.x;
    const int warp = tid >> 5;
    const int lane = tid & 31;
    const int tok0 = blockIdx.x * GTOK;

    // stage x
    {
        const float4* src = (const float4*)(x + (size_t)tok0 * DIM);
        float4* dst = (float4*)x_s;
        #pragma unroll
        for (int i = tid; i < GTOK * DIM / 4; i += 256) dst[i] = src[i];
    }
    __syncthreads();

    // ---- distance + argmin: 128 (branch, codebook) pairs over 8 warps ----
    for (int pair = warp; pair < 2 * NCB; pair += 8) {
        const int br = pair >> 6;
        const int c  = pair & 63;
        const float* emb = br ? emb_B : emb_A;
        // two key rows per lane: p0 = lane, p1 = lane+32 (regs, reused over 8 tokens)
        float e0[KD], e1[KD];
        {
            const float4* r0 = (const float4*)(emb + ((size_t)c * NP + lane) * KD);
            const float4* r1 = r0 + 32 * KD / 4;
            #pragma unroll
            for (int q = 0; q < 4; q++) {
                float4 v0 = __ldg(r0 + q), v1 = __ldg(r1 + q);
                e0[q*4+0]=v0.x; e0[q*4+1]=v0.y; e0[q*4+2]=v0.z; e0[q*4+3]=v0.w;
                e1[q*4+0]=v1.x; e1[q*4+1]=v1.y; e1[q*4+2]=v1.z; e1[q*4+3]=v1.w;
            }
        }
        float ee0 = 0.f, ee1 = 0.f;
        #pragma unroll
        for (int k = 0; k < KD; k++) { ee0 = fmaf(e0[k], e0[k], ee0); ee1 = fmaf(e1[k], e1[k], ee1); }

        #pragma unroll
        for (int g = 0; g < GTOK; g++) {
            const float4* pr = (const float4*)(proj + (size_t)(tok0 + g) * NPROJ
                                               + br * 1024 + c * KD);
            float p[KD];
            #pragma unroll
            for (int q = 0; q < 4; q++) {
                float4 v = __ldg(pr + q);
                p[q*4+0]=v.x; p[q*4+1]=v.y; p[q*4+2]=v.z; p[q*4+3]=v.w;
            }
            float pp = 0.f, d0 = 0.f, d1 = 0.f;
            #pragma unroll
            for (int k = 0; k < KD; k++) {
                pp = fmaf(p[k], p[k], pp);
                d0 = fmaf(p[k], e0[k], d0);
                d1 = fmaf(p[k], e1[k], d1);
            }
            // same expression as reference: (pp - 2*dot) + ee
            float s0 = (pp - 2.0f * d0) + ee0;
            float s1 = (pp - 2.0f * d1) + ee1;
            unsigned u = ord_f32(s0); int bi = lane;
            unsigned u1 = ord_f32(s1);
            if (u1 < u) { u = u1; bi = lane + 32; }     // strict: tie keeps lower idx
            unsigned umin = __reduce_min_sync(0xffffffffu, u);
            unsigned cand = (u == umin) ? (unsigned)bi : 0xffffffffu;
            unsigned imin = __reduce_min_sync(0xffffffffu, cand);
            if (lane == 0) (br ? idxB : idxA)[g * NCB + c] = (int)imin;
        }
    }
    __syncthreads();

    // ---- s_A[c] = dot(x_chunk[c%8], vals_A[c, idxA[c]]) ----
    for (int c = warp; c < NCB; c += 8) {
        const int chunk = c & 7;
        #pragma unroll
        for (int g = 0; g < GTOK; g++) {
            const int id = idxA[g * NCB + c];
            const float* vr = vals_A + ((size_t)c * NP + id) * MV;
            const float* xr = x_s + g * DIM + chunk * MV;
            float acc = 0.f;
            #pragma unroll
            for (int j = 0; j < 4; j++) {
                int m = lane + 32 * j;
                acc = fmaf(xr[m], __ldg(vr + m), acc);
            }
            #pragma unroll
            for (int off = 16; off > 0; off >>= 1)
                acc += __shfl_xor_sync(0xffffffffu, acc, off);
            if (lane == 0) sA[g * NCB + c] = acc;
        }
    }
    __syncthreads();

    // ---- t[g][r] = sum of 8 consecutive s ----
    if (tid < GTOK * NR) {
        const int g = tid >> 3, r = tid & 7;
        float acc = 0.f;
        #pragma unroll
        for (int i = 0; i < 8; i++) acc += sA[g * NCB + r * 8 + i];
        tb[g * NR + r] = acc;
    }
    __syncthreads();

    // ---- out[token][h*128+m] = sum_r t[r] * vals_B[8r+h, idxB[8r+h], m] ----
    for (int g = 0; g < GTOK; g++) {
        float tr[NR];
        #pragma unroll
        for (int r = 0; r < NR; r++) tr[r] = tb[g * NR + r];
        float* orow = out + (size_t)(tok0 + g) * DIM;
        #pragma unroll
        for (int j = 0; j < 4; j++) {
            const int d = tid + 256 * j;
            const int h = d >> 7, m = d & 127;
            float acc = 0.f;
            #pragma unroll
            for (int r = 0; r < NR; r++) {
                const int c = 8 * r + h;
                acc = fmaf(tr[r],
                           __ldg(vals_B + ((size_t)c * NP + idxB[g * NCB + c]) * MV + m),
                           acc);
            }
            orow[d] = acc;
        }
    }
}

// ---------------------------------------------------------------------------
extern "C" void kernel_launch(void* const* d_in, const int* in_sizes, int n_in,
                              void* d_out, int out_size)
{
    (void)in_sizes; (void)n_in; (void)out_size;
    const float* x      = (const float*)d_in[0];
    const float* W_A    = (const float*)d_in[1];
    const float* emb_A  = (const float*)d_in[2];
    const float* vals_A = (const float*)d_in[3];
    const float* W_B    = (const float*)d_in[4];
    const float* emb_B  = (const float*)d_in[5];
    const float* vals_B = (const float*)d_in[6];
    float* out = (float*)d_out;

    float* proj;
    cudaGetSymbolAddress((void**)&proj, g_proj);

    dim3 gg(NPROJ / 128, TOK / 128);
    proj_gemm<<<gg, 256>>>(x, W_A, W_B, proj);
    fuse_kernel<<<TOK / GTOK, 256>>>(x, proj, emb_A, vals_A, emb_B, vals_B, out);
}

// round 4
// speedup vs baseline: 1.1183x; 1.1183x over previous
#include <cuda_runtime.h>
#include <cstdint>

// Problem dims (fixed)
#define TOK   8192      // B*N
#define DIM   1024      // D
#define NCB   64        // C codebooks
#define KD    16        // K
#define NP    64        // P keys
#define MV    128       // M
#define NR    8         // R
#define NPROJ 2048      // 2 branches * C*K

// 64 MB scratch for projections: proj[t][n], n = branch*1024 + c*16 + k
__device__ float g_proj[(size_t)TOK * NPROJ];

// ---------------------------------------------------------------------------
// Kernel 1: fp32 SGEMM  proj[t, n] = sum_d x[t,d] * W[n,d]
// 128x128 tile, BK=16, 256 threads, 8x8 micro-tile, double-buffered smem,
// one __syncthreads per 16-deep k-step.
// ---------------------------------------------------------------------------
__global__ __launch_bounds__(256) void proj_gemm(
    const float* __restrict__ X,
    const float* __restrict__ WA,
    const float* __restrict__ WB,
    float* __restrict__ out)
{
    const int n0 = blockIdx.x * 128;   // 0..1920
    const int t0 = blockIdx.y * 128;   // 0..8064
    const float* __restrict__ W = (n0 < 1024) ? (WA + (size_t)n0 * DIM)
                                              : (WB + (size_t)(n0 - 1024) * DIM);

    __shared__ float As[2][16][128];
    __shared__ float Bs[2][16][128];

    const int tid = threadIdx.x;
    const int tx = tid & 15;        // 0..15 -> n
    const int ty = tid >> 4;        // 0..15 -> t
    const int lr = tid >> 1;        // 0..127 load row
    const int lc = (tid & 1) * 8;   // 0 or 8 load col base

    float acc[8][8];
    #pragma unroll
    for (int i = 0; i < 8; i++)
        #pragma unroll
        for (int j = 0; j < 8; j++) acc[i][j] = 0.f;

    const float* aptr = X + (size_t)(t0 + lr) * DIM + lc;
    const float* bptr = W + (size_t)lr * DIM + lc;

    // preload k0 = 0
    float4 av0 = *(const float4*)(aptr);
    float4 av1 = *(const float4*)(aptr + 4);
    float4 bv0 = *(const float4*)(bptr);
    float4 bv1 = *(const float4*)(bptr + 4);
    As[0][lc+0][lr]=av0.x; As[0][lc+1][lr]=av0.y; As[0][lc+2][lr]=av0.z; As[0][lc+3][lr]=av0.w;
    As[0][lc+4][lr]=av1.x; As[0][lc+5][lr]=av1.y; As[0][lc+6][lr]=av1.z; As[0][lc+7][lr]=av1.w;
    Bs[0][lc+0][lr]=bv0.x; Bs[0][lc+1][lr]=bv0.y; Bs[0][lc+2][lr]=bv0.z; Bs[0][lc+3][lr]=bv0.w;
    Bs[0][lc+4][lr]=bv1.x; Bs[0][lc+5][lr]=bv1.y; Bs[0][lc+6][lr]=bv1.z; Bs[0][lc+7][lr]=bv1.w;
    __syncthreads();

    int buf = 0;
    for (int k0 = 16; k0 < DIM; k0 += 16) {
        // next-tile loads issued early, hidden under compute
        av0 = *(const float4*)(aptr + k0);
        av1 = *(const float4*)(aptr + k0 + 4);
        bv0 = *(const float4*)(bptr + k0);
        bv1 = *(const float4*)(bptr + k0 + 4);

        #pragma unroll
        for (int kk = 0; kk < 16; kk++) {
            float ra[8], rb[8];
            #pragma unroll
            for (int i = 0; i < 8; i++) ra[i] = As[buf][kk][ty * 8 + i];
            #pragma unroll
            for (int j = 0; j < 8; j++) rb[j] = Bs[buf][kk][tx * 8 + j];
            #pragma unroll
            for (int i = 0; i < 8; i++)
                #pragma unroll
                for (int j = 0; j < 8; j++)
                    acc[i][j] = fmaf(ra[i], rb[j], acc[i][j]);
        }

        const int nb = buf ^ 1;
        As[nb][lc+0][lr]=av0.x; As[nb][lc+1][lr]=av0.y; As[nb][lc+2][lr]=av0.z; As[nb][lc+3][lr]=av0.w;
        As[nb][lc+4][lr]=av1.x; As[nb][lc+5][lr]=av1.y; As[nb][lc+6][lr]=av1.z; As[nb][lc+7][lr]=av1.w;
        Bs[nb][lc+0][lr]=bv0.x; Bs[nb][lc+1][lr]=bv0.y; Bs[nb][lc+2][lr]=bv0.z; Bs[nb][lc+3][lr]=bv0.w;
        Bs[nb][lc+4][lr]=bv1.x; Bs[nb][lc+5][lr]=bv1.y; Bs[nb][lc+6][lr]=bv1.z; Bs[nb][lc+7][lr]=bv1.w;
        __syncthreads();
        buf = nb;
    }

    // last tile
    #pragma unroll
    for (int kk = 0; kk < 16; kk++) {
        float ra[8], rb[8];
        #pragma unroll
        for (int i = 0; i < 8; i++) ra[i] = As[buf][kk][ty * 8 + i];
        #pragma unroll
        for (int j = 0; j < 8; j++) rb[j] = Bs[buf][kk][tx * 8 + j];
        #pragma unroll
        for (int i = 0; i < 8; i++)
            #pragma unroll
            for (int j = 0; j < 8; j++)
                acc[i][j] = fmaf(ra[i], rb[j], acc[i][j]);
    }

    #pragma unroll
    for (int i = 0; i < 8; i++) {
        float* orow = out + (size_t)(t0 + ty * 8 + i) * NPROJ + n0 + tx * 8;
        *(float4*)(orow + 0) = make_float4(acc[i][0], acc[i][1], acc[i][2], acc[i][3]);
        *(float4*)(orow + 4) = make_float4(acc[i][4], acc[i][5], acc[i][6], acc[i][7]);
    }
}

// ---------------------------------------------------------------------------
// Kernel 2: fused argmin + gather-dot + output.  8 tokens per block.
// proj staged in smem via cp.async (R1 evidence: staged argmin >> gmem argmin).
// x is NOT staged: sA phase holds x-chunk in registers with 8x reuse.
// ---------------------------------------------------------------------------
#define GTOK 8
#define FUSE_SMEM (GTOK * NPROJ * 4)   // 64 KB dynamic

__device__ __forceinline__ unsigned ord_f32(float f) {
    unsigned b = __float_as_uint(f);
    return (b & 0x80000000u) ? ~b : (b | 0x80000000u);  // monotonic map
}

__global__ __launch_bounds__(256) void fuse_kernel(
    const float* __restrict__ x,
    const float* __restrict__ proj,
    const float* __restrict__ emb_A, const float* __restrict__ vals_A,
    const float* __restrict__ emb_B, const float* __restrict__ vals_B,
    float* __restrict__ out)
{
    extern __shared__ float proj_s[];            // GTOK*2048 floats
    __shared__ float sA[GTOK * NCB];
    __shared__ float tb[GTOK * NR];
    __shared__ int   idxA[GTOK * NCB];
    __shared__ int   idxB[GTOK * NCB];

    const int tid  = threadIdx.x;
    const int warp = tid >> 5;
    const int lane = tid & 31;
    const int tok0 = blockIdx.x * GTOK;

    // ---- stage proj via cp.async (bulk, coalesced, no reg round-trip) ----
    {
        const float* src = proj + (size_t)tok0 * NPROJ;
        unsigned sdst = (unsigned)__cvta_generic_to_shared(proj_s);
        #pragma unroll
        for (int i = tid; i < GTOK * NPROJ / 4; i += 256) {
            asm volatile("cp.async.cg.shared.global [%0], [%1], 16;"
                         :: "r"(sdst + i * 16), "l"(src + i * 4));
        }
        asm volatile("cp.async.commit_group;");
        asm volatile("cp.async.wait_group 0;");
    }
    __syncthreads();

    // ---- distance + argmin: 128 (branch, codebook) pairs over 8 warps ----
    for (int pair = warp; pair < 2 * NCB; pair += 8) {
        const int br = pair >> 6;
        const int c  = pair & 63;
        const float* emb = br ? emb_B : emb_A;
        // two key rows per lane: p0 = lane, p1 = lane+32 (regs, reused over 8 tokens)
        float e0[KD], e1[KD];
        {
            const float4* r0 = (const float4*)(emb + ((size_t)c * NP + lane) * KD);
            const float4* r1 = r0 + 32 * KD / 4;
            #pragma unroll
            for (int q = 0; q < 4; q++) {
                float4 v0 = __ldg(r0 + q), v1 = __ldg(r1 + q);
                e0[q*4+0]=v0.x; e0[q*4+1]=v0.y; e0[q*4+2]=v0.z; e0[q*4+3]=v0.w;
                e1[q*4+0]=v1.x; e1[q*4+1]=v1.y; e1[q*4+2]=v1.z; e1[q*4+3]=v1.w;
            }
        }
        float ee0 = 0.f, ee1 = 0.f;
        #pragma unroll
        for (int k = 0; k < KD; k++) { ee0 = fmaf(e0[k], e0[k], ee0); ee1 = fmaf(e1[k], e1[k], ee1); }

        #pragma unroll
        for (int g = 0; g < GTOK; g++) {
            const float4* pr = (const float4*)(proj_s + g * NPROJ + br * 1024 + c * KD);
            float p[KD];
            #pragma unroll
            for (int q = 0; q < 4; q++) {
                float4 v = pr[q];   // broadcast LDS.128: all lanes same addr
                p[q*4+0]=v.x; p[q*4+1]=v.y; p[q*4+2]=v.z; p[q*4+3]=v.w;
            }
            float pp = 0.f, d0 = 0.f, d1 = 0.f;
            #pragma unroll
            for (int k = 0; k < KD; k++) {
                pp = fmaf(p[k], p[k], pp);
                d0 = fmaf(p[k], e0[k], d0);
                d1 = fmaf(p[k], e1[k], d1);
            }
            // same expression as reference: (pp - 2*dot) + ee
            float s0 = (pp - 2.0f * d0) + ee0;
            float s1 = (pp - 2.0f * d1) + ee1;
            // packed lexicographic (score, idx) min -> first-occurrence argmin
            unsigned long long k0 = ((unsigned long long)ord_f32(s0) << 6) | (unsigned)lane;
            unsigned long long k1 = ((unsigned long long)ord_f32(s1) << 6) | (unsigned)(lane + 32);
            unsigned long long key = (k1 < k0) ? k1 : k0;
            #pragma unroll
            for (int off = 16; off > 0; off >>= 1) {
                unsigned long long o = __shfl_xor_sync(0xffffffffu, key, off);
                if (o < key) key = o;
            }
            if (lane == 0) (br ? idxB : idxA)[g * NCB + c] = (int)(key & 63u);
        }
    }
    __syncthreads();

    // ---- sA: warp per (token, chunk); x-chunk in regs, 8x reuse over c ----
    for (int task = warp; task < GTOK * 8; task += 8) {
        const int g = task >> 3, chunk = task & 7;
        float4 xr = *(const float4*)(x + (size_t)(tok0 + g) * DIM + chunk * MV + lane * 4);
        float acc[8];
        #pragma unroll
        for (int ci = 0; ci < 8; ci++) {
            const int c = ci * 8 + chunk;          // c % 8 == chunk
            const int id = idxA[g * NCB + c];
            float4 vr = __ldg((const float4*)(vals_A + ((size_t)c * NP + id) * MV) + lane);
            acc[ci] = xr.x*vr.x + xr.y*vr.y + xr.z*vr.z + xr.w*vr.w;
        }
        #pragma unroll
        for (int off = 16; off > 0; off >>= 1)
            #pragma unroll
            for (int ci = 0; ci < 8; ci++)
                acc[ci] += __shfl_xor_sync(0xffffffffu, acc[ci], off);
        if (lane == 0) {
            #pragma unroll
            for (int ci = 0; ci < 8; ci++)
                sA[g * NCB + ci * 8 + chunk] = acc[ci];
        }
    }
    __syncthreads();

    // ---- t[g][r] = sum of 8 consecutive s ----
    if (tid < GTOK * NR) {
        const int g = tid >> 3, r = tid & 7;
        float acc = 0.f;
        #pragma unroll
        for (int i = 0; i < 8; i++) acc += sA[g * NCB + r * 8 + i];
        tb[g * NR + r] = acc;
    }
    __syncthreads();

    // ---- out[token][h*128+m] = sum_r t[r] * vals_B[8r+h, idxB[8r+h], m] ----
    for (int g = 0; g < GTOK; g++) {
        float tr[NR];
        #pragma unroll
        for (int r = 0; r < NR; r++) tr[r] = tb[g * NR + r];
        float* orow = out + (size_t)(tok0 + g) * DIM;
        #pragma unroll
        for (int j = 0; j < 4; j++) {
            const int d = tid + 256 * j;
            const int h = d >> 7, m = d & 127;
            float acc = 0.f;
            #pragma unroll
            for (int r = 0; r < NR; r++) {
                const int c = 8 * r + h;
                acc = fmaf(tr[r],
                           __ldg(vals_B + ((size_t)c * NP + idxB[g * NCB + c]) * MV + m),
                           acc);
            }
            orow[d] = acc;
        }
    }
}

// ---------------------------------------------------------------------------
extern "C" void kernel_launch(void* const* d_in, const int* in_sizes, int n_in,
                              void* d_out, int out_size)
{
    (void)in_sizes; (void)n_in; (void)out_size;
    const float* x      = (const float*)d_in[0];
    const float* W_A    = (const float*)d_in[1];
    const float* emb_A  = (const float*)d_in[2];
    const float* vals_A = (const float*)d_in[3];
    const float* W_B    = (const float*)d_in[4];
    const float* emb_B  = (const float*)d_in[5];
    const float* vals_B = (const float*)d_in[6];
    float* out = (float*)d_out;

    float* proj;
    cudaGetSymbolAddress((void**)&proj, g_proj);

    static bool attr_set = false;
    if (!attr_set) {
        cudaFuncSetAttribute(fuse_kernel,
                             cudaFuncAttributeMaxDynamicSharedMemorySize, FUSE_SMEM);
        attr_set = true;
    }

    dim3 gg(NPROJ / 128, TOK / 128);
    proj_gemm<<<gg, 256>>>(x, W_A, W_B, proj);
    fuse_kernel<<<TOK / GTOK, 256, FUSE_SMEM>>>(x, proj, emb_A, vals_A, emb_B, vals_B, out);
}